// round 15
// baseline (speedup 1.0000x reference)
#include <cuda_runtime.h>

#define NB 16
#define NN 4096
#define NE 131072
#define NH 16
#define NT 3
#define NFC 20
#define BHD 256                     // B*H = 256 floats per node row
#define INV_SQRT_DEG 0.17677669529663687f   // 1/sqrt(E/N) = 1/sqrt(32)

#define KSPLIT 16                   // j-reduction splits in k_gemm
#define GROWS 128                   // rows per gemm block (512 blocks -> better waves/overlap)
#define MROWS (GROWS / 32)          // 4 row-fragments per thread
#define KJ 32                       // j-chunk per smem stage
#define WPITCH 34                   // Ws smem pitch (34 mod 32 == 2 -> LDS.64 conflict-free)
#define SCAT_BLKS (NE / 1024)       // 128 scatter blocks

typedef unsigned long long ull;

// ---------------- device scratch (static: no allocs allowed) ----------------
__device__ __align__(16) float g_h0[NN * BHD];     // final-h buffer (layer1 out)
__device__ __align__(16) float g_h1[NN * BHD];     // layer0 out
__device__ __align__(16) float g_A[NN * 48];       // a[i][b*3+p]
__device__ __align__(16) float g_C[NN * 48];       // c[j][b*3+q]
__device__ __align__(16) float g_R[KSPLIT * 48 * NN];  // R partials [sp][col][i]
__device__ int   g_cnt[NN];                        // zero-init; re-zeroed by k_scan
__device__ int   g_rowptr[NN + 1];
__device__ int   g_cursor[NN];
__device__ int   g_csr[NE];                        // src | (type<<16), sorted by dst
__device__ float g_ew[2 * NT];                     // per-layer per-type edge weight
__device__ float g_invF[NB * 9];
__device__ float g_P[NB * NH * 3];                 // P[b,k,j] = sum_i F[b,i,j] * W_in[i,k]
__device__ float g_S[NN * 3];                      // zero-init; re-zeroed by k_layer1

// ---------------- f32x2 packed-FMA helpers ----------------
__device__ __forceinline__ ull pk2(float lo, float hi) {
    ull r;
    asm("mov.b64 %0, {%1, %2};" : "=l"(r) : "f"(lo), "f"(hi));
    return r;
}
__device__ __forceinline__ void upk2(ull v, float& lo, float& hi) {
    asm("mov.b64 {%0, %1}, %2;" : "=f"(lo), "=f"(hi) : "l"(v));
}
__device__ __forceinline__ void fma2(ull& d, ull a, ull b) {
    asm("fma.rn.f32x2 %0, %1, %2, %0;" : "+l"(d) : "l"(a), "l"(b));
}

// ---- hist: cnt histogram + S accumulation + one-time init (block 0) ----
__global__ void k_hist(const int* __restrict__ edge_dst, const int* __restrict__ edge_src,
                       const int* __restrict__ edge_type, const float* __restrict__ node_pos,
                       const float* __restrict__ F, const float* __restrict__ W_in,
                       const float* __restrict__ fc10, const float* __restrict__ fc20,
                       const float* __restrict__ fc11, const float* __restrict__ fc21) {
    int tid = threadIdx.x;
    float ew0 = 0.f, ew1 = 0.f, ew2 = 0.f;
    #pragma unroll
    for (int f = 0; f < NFC; f++) {
        float c2 = __ldg(&fc20[f]);
        ew0 = fmaf(fmaxf(__ldg(&fc10[f]), 0.f), c2, ew0);
        ew1 = fmaf(fmaxf(__ldg(&fc10[NFC + f]), 0.f), c2, ew1);
        ew2 = fmaf(fmaxf(__ldg(&fc10[2 * NFC + f]), 0.f), c2, ew2);
    }
    int e0 = blockIdx.x * 1024 + tid * 4;
    int4 d4 = *(const int4*)(edge_dst + e0);
    int4 s4 = *(const int4*)(edge_src + e0);
    int4 t4 = *(const int4*)(edge_type + e0);
    int ds[4] = {d4.x, d4.y, d4.z, d4.w};
    int ss[4] = {s4.x, s4.y, s4.z, s4.w};
    int ts[4] = {t4.x, t4.y, t4.z, t4.w};
    #pragma unroll
    for (int u = 0; u < 4; u++) {
        int d = ds[u], s = ss[u], t = ts[u];
        atomicAdd(&g_cnt[d], 1);
        float w = (t == 0) ? ew0 : ((t == 1) ? ew1 : ew2);
        atomicAdd(&g_S[d * 3 + 0], w * __ldg(&node_pos[s * 3 + 0]));
        atomicAdd(&g_S[d * 3 + 1], w * __ldg(&node_pos[s * 3 + 1]));
        atomicAdd(&g_S[d * 3 + 2], w * __ldg(&node_pos[s * 3 + 2]));
    }
    if (blockIdx.x == 0) {
        if (tid < 6) {
            int l = tid / 3, t = tid % 3;
            const float* f1 = l ? fc11 : fc10;
            const float* f2 = l ? fc21 : fc20;
            float s = 0.f;
            #pragma unroll
            for (int f = 0; f < NFC; f++) s = fmaf(fmaxf(f1[t * NFC + f], 0.f), f2[f], s);
            g_ew[tid] = s;
        }
        if (tid >= 32 && tid < 32 + NB) {
            int b = tid - 32;
            const float* m = F + b * 9;
            float a00=m[0],a01=m[1],a02=m[2],a10=m[3],a11=m[4],a12=m[5],a20=m[6],a21=m[7],a22=m[8];
            float det = a00*(a11*a22-a12*a21) - a01*(a10*a22-a12*a20) + a02*(a10*a21-a11*a20);
            float id = 1.f / det;
            float* o = g_invF + b * 9;
            o[0]=(a11*a22-a12*a21)*id; o[1]=(a02*a21-a01*a22)*id; o[2]=(a01*a12-a02*a11)*id;
            o[3]=(a12*a20-a10*a22)*id; o[4]=(a00*a22-a02*a20)*id; o[5]=(a02*a10-a00*a12)*id;
            o[6]=(a10*a21-a11*a20)*id; o[7]=(a01*a20-a00*a21)*id; o[8]=(a00*a11-a01*a10)*id;
        }
        for (int idx = tid; idx < NB * NH * 3; idx += 256) {
            int b = idx / 48, r = idx % 48, k = r / 3, j = r % 3;
            float s = 0.f;
            #pragma unroll
            for (int i = 0; i < 3; i++) s = fmaf(F[b * 9 + i * 3 + j], W_in[i * 16 + k], s);
            g_P[idx] = s;
        }
    }
}

// ---------------- scan (1 block) + re-zero cnt ----------------
__global__ void k_scan() {
    int tid = threadIdx.x;
    int v[4]; int s = 0;
    #pragma unroll
    for (int j = 0; j < 4; j++) { v[j] = g_cnt[tid * 4 + j]; s += v[j]; }
    #pragma unroll
    for (int j = 0; j < 4; j++) g_cnt[tid * 4 + j] = 0;
    int lane = tid & 31, wid = tid >> 5;
    const unsigned full = 0xFFFFFFFFu;
    int x = s;
    #pragma unroll
    for (int off = 1; off < 32; off <<= 1) { int y = __shfl_up_sync(full, x, off); if (lane >= off) x += y; }
    __shared__ int swarp[32];
    if (lane == 31) swarp[wid] = x;
    __syncthreads();
    if (wid == 0) {
        int y = swarp[lane];
        #pragma unroll
        for (int off = 1; off < 32; off <<= 1) { int z = __shfl_up_sync(full, y, off); if (lane >= off) y += z; }
        swarp[lane] = y;
    }
    __syncthreads();
    int base = (x - s) + (wid > 0 ? swarp[wid - 1] : 0);
    int run = base;
    #pragma unroll
    for (int j = 0; j < 4; j++) {
        g_rowptr[tid * 4 + j] = run;
        g_cursor[tid * 4 + j] = run;
        run += v[j];
    }
    if (tid == 1023) g_rowptr[NN] = run;
}

// ---- fused: blocks [0,128) build CSR; blocks [128,640) run layer0 closed form ----
__global__ void k_scatter_l0(const int* __restrict__ edge_src,
                             const int* __restrict__ edge_dst,
                             const int* __restrict__ edge_type,
                             const float* __restrict__ W0) {
    int tid = threadIdx.x;
    if (blockIdx.x < SCAT_BLKS) {
        int e0 = blockIdx.x * 1024 + tid * 4;
        int4 d4 = *(const int4*)(edge_dst + e0);
        int4 s4 = *(const int4*)(edge_src + e0);
        int4 t4 = *(const int4*)(edge_type + e0);
        int ds[4] = {d4.x, d4.y, d4.z, d4.w};
        int ss[4] = {s4.x, s4.y, s4.z, s4.w};
        int ts[4] = {t4.x, t4.y, t4.z, t4.w};
        #pragma unroll
        for (int u = 0; u < 4; u++) {
            int pos = atomicAdd(&g_cursor[ds[u]], 1);
            g_csr[pos] = ss[u] | (ts[u] << 16);
        }
        return;
    }
    // ---- layer0 (8 nodes/block) ----
    int bid = blockIdx.x - SCAT_BLKS;
    __shared__ float sW[256], sS[24];
    __shared__ float sagg[8][256];
    sW[tid] = W0[tid];
    if (tid < 24) sS[tid] = g_S[bid * 24 + tid];
    float p0 = g_P[tid * 3], p1 = g_P[tid * 3 + 1], p2 = g_P[tid * 3 + 2];
    __syncthreads();
    #pragma unroll
    for (int nn = 0; nn < 8; nn++) {
        float acc = fmaf(p2, sS[nn * 3 + 2], fmaf(p1, sS[nn * 3 + 1], p0 * sS[nn * 3]));
        sagg[nn][tid] = acc * INV_SQRT_DEG;
    }
    __syncthreads();
    int b = tid >> 4, k = tid & 15;
    #pragma unroll
    for (int nn = 0; nn < 8; nn++) {
        const float* ar = &sagg[nn][b * 16];
        float s = 0.f;
        #pragma unroll
        for (int kk = 0; kk < 16; kk++) s = fmaf(ar[kk], sW[kk * 16 + k], s);
        g_h1[(bid * 8 + nn) * BHD + tid] = fmaxf(s, 0.f);
    }
}

// ---------------- layer 1: float4 gather, manual 4x unroll for MLP (R13 exact) ----------------
__global__ void k_layer1(const float* __restrict__ W1) {
    int n = blockIdx.x, tid = threadIdx.x;
    __shared__ float sW[256], sagg[256], sew[3];
    __shared__ __align__(16) float4 s4[4][64];
    __shared__ int sedge[128];
    sW[tid] = W1[tid];
    if (tid < 3) sew[tid] = g_ew[3 + tid];
    if (tid >= 32 && tid < 35) g_S[n * 3 + (tid - 32)] = 0.f;   // reset for next replay
    int g = tid >> 6, c4 = tid & 63;
    int start = g_rowptr[n], end = g_rowptr[n + 1];
    float4 acc = make_float4(0.f, 0.f, 0.f, 0.f);
    for (int base = start; base < end; base += 128) {
        int cnt = min(128, end - base);
        __syncthreads();
        if (tid < cnt) sedge[tid] = g_csr[base + tid];
        __syncthreads();
        int i = g;
        for (; i + 12 < cnt; i += 16) {
            int p0 = sedge[i], p1 = sedge[i + 4], p2 = sedge[i + 8], p3 = sedge[i + 12];
            float4 v0 = __ldg((const float4*)(g_h1 + (p0 & 0xFFFF) * BHD) + c4);
            float4 v1 = __ldg((const float4*)(g_h1 + (p1 & 0xFFFF) * BHD) + c4);
            float4 v2 = __ldg((const float4*)(g_h1 + (p2 & 0xFFFF) * BHD) + c4);
            float4 v3 = __ldg((const float4*)(g_h1 + (p3 & 0xFFFF) * BHD) + c4);
            float w0 = sew[p0 >> 16], w1 = sew[p1 >> 16];
            float w2 = sew[p2 >> 16], w3 = sew[p3 >> 16];
            acc.x = fmaf(w0, v0.x, acc.x); acc.y = fmaf(w0, v0.y, acc.y);
            acc.z = fmaf(w0, v0.z, acc.z); acc.w = fmaf(w0, v0.w, acc.w);
            acc.x = fmaf(w1, v1.x, acc.x); acc.y = fmaf(w1, v1.y, acc.y);
            acc.z = fmaf(w1, v1.z, acc.z); acc.w = fmaf(w1, v1.w, acc.w);
            acc.x = fmaf(w2, v2.x, acc.x); acc.y = fmaf(w2, v2.y, acc.y);
            acc.z = fmaf(w2, v2.z, acc.z); acc.w = fmaf(w2, v2.w, acc.w);
            acc.x = fmaf(w3, v3.x, acc.x); acc.y = fmaf(w3, v3.y, acc.y);
            acc.z = fmaf(w3, v3.z, acc.z); acc.w = fmaf(w3, v3.w, acc.w);
        }
        for (; i < cnt; i += 4) {
            int p = sedge[i];
            float w = sew[p >> 16];
            float4 v = __ldg((const float4*)(g_h1 + (p & 0xFFFF) * BHD) + c4);
            acc.x = fmaf(w, v.x, acc.x);
            acc.y = fmaf(w, v.y, acc.y);
            acc.z = fmaf(w, v.z, acc.z);
            acc.w = fmaf(w, v.w, acc.w);
        }
    }
    s4[g][c4] = acc;
    __syncthreads();
    {
        const float* sf = (const float*)s4;
        float a = sf[tid] + sf[256 + tid] + sf[512 + tid] + sf[768 + tid];
        sagg[tid] = a * INV_SQRT_DEG;
    }
    __syncthreads();
    int b = tid >> 4, k = tid & 15;
    const float* ar = &sagg[b * 16];
    float s = 0.f;
    #pragma unroll
    for (int kk = 0; kk < 16; kk++) s = fmaf(ar[kk], sW[kk * 16 + k], s);
    g_h0[n * BHD + tid] = fmaxf(s, 0.f);
}

// ---------------- head (4 edges/block): a & c for the first N edges ----------------
__global__ void k_head(const int* __restrict__ edge_src, const int* __restrict__ edge_dst,
                       const float* __restrict__ W_out) {
    int tid = threadIdx.x;
    int g = tid >> 6, c4 = tid & 63;
    int e0 = blockIdx.x * 4;
    __shared__ __align__(16) float4 sd4[4][64];
    __shared__ float sa[4][48];
    {
        int e = e0 + g;
        int src = edge_src[e], dst = edge_dst[e];
        float4 vs = __ldg((const float4*)(g_h0 + src * BHD) + c4);
        float4 vd = __ldg((const float4*)(g_h0 + dst * BHD) + c4);
        sd4[g][c4] = make_float4(vs.x - vd.x, vs.y - vd.y, vs.z - vd.z, vs.w - vd.w);
    }
    __syncthreads();
    if (tid < 192) {
        int eg = tid / 48, r = tid % 48;
        int b = r / 3, p = r % 3;
        const float* sd = (const float*)sd4[eg];
        float a = 0.f;
        #pragma unroll
        for (int k = 0; k < 16; k++) a = fmaf(sd[b * 16 + k], __ldg(&W_out[k * 3 + p]), a);
        sa[eg][r] = a;
        g_A[(e0 + eg) * 48 + r] = a;
    }
    __syncthreads();
    if (tid < 192) {
        int eg = tid / 48, r = tid % 48;
        int b = r / 3, q = r % 3;
        float c = 0.f;
        #pragma unroll
        for (int p = 0; p < 3; p++) c = fmaf(g_invF[b * 9 + q * 3 + p], sa[eg][b * 3 + p], c);
        g_C[(e0 + eg) * 48 + r] = c;
    }
}

// ---------------- R = W2 @ C via packed f32x2 FFMA; R stored [sp][col][i] ----------------
// GROWS=128: 512 blocks, 23.4 KB smem -> multiple blocks/SM overlap staging & math.
__global__ void __launch_bounds__(256) k_gemm(const float* __restrict__ W2) {
    int i0 = blockIdx.x * GROWS;
    int js = blockIdx.y;
    int j0base = js * (NN / KSPLIT);             // 256 j's per split
    __shared__ float Ws[GROWS * WPITCH];         // 128 x 34 floats = 17.4 KB
    __shared__ __align__(16) float Cs[KJ * 48];  // 6 KB
    int tid = threadIdx.x;
    int tr = tid & 31, tc = tid >> 5;

    ull acc[MROWS][3];
    #pragma unroll
    for (int m = 0; m < MROWS; m++)
        #pragma unroll
        for (int u = 0; u < 3; u++) acc[m][u] = 0ull;

    #pragma unroll 1
    for (int jc = 0; jc < (NN / KSPLIT) / KJ; jc++) {
        int j0 = j0base + jc * KJ;
        __syncthreads();
        {
            const float4* cg = (const float4*)(g_C + j0 * 48);
            float4* cs = (float4*)Cs;
            for (int t = tid; t < KJ * 12; t += 256) cs[t] = cg[t];
        }
        #pragma unroll
        for (int rep = 0; rep < GROWS * 8 / 256; rep++) {   // 4 reps
            int f = rep * 256 + tid;
            int r = f >> 3, c4 = f & 7;
            float4 w = *(const float4*)(W2 + (size_t)(i0 + r) * NN + j0 + c4 * 4);
            float* wd = &Ws[r * WPITCH + c4 * 4];
            wd[0] = w.x; wd[1] = w.y; wd[2] = w.z; wd[3] = w.w;
        }
        __syncthreads();
        #pragma unroll
        for (int jj = 0; jj < KJ; jj += 2) {
            float2 wv[MROWS];
            #pragma unroll
            for (int m = 0; m < MROWS; m++)
                wv[m] = *(const float2*)&Ws[(tr + 32 * m) * WPITCH + jj];
            const float2* c0 = (const float2*)&Cs[jj * 48 + tc * 6];
            const float2* c1 = (const float2*)&Cs[(jj + 1) * 48 + tc * 6];
            ull ca0 = ((const ull*)c0)[0];
            ull ca1 = ((const ull*)c0)[1];
            ull ca2 = ((const ull*)c0)[2];
            ull cb0 = ((const ull*)c1)[0];
            ull cb1 = ((const ull*)c1)[1];
            ull cb2 = ((const ull*)c1)[2];
            #pragma unroll
            for (int m = 0; m < MROWS; m++) {
                ull wlo = pk2(wv[m].x, wv[m].x);
                ull whi = pk2(wv[m].y, wv[m].y);
                fma2(acc[m][0], wlo, ca0);
                fma2(acc[m][1], wlo, ca1);
                fma2(acc[m][2], wlo, ca2);
                fma2(acc[m][0], whi, cb0);
                fma2(acc[m][1], whi, cb1);
                fma2(acc[m][2], whi, cb2);
            }
        }
    }
    // epilogue: R[sp][col][i], coalesced over i
    float* outp = g_R + (size_t)js * 48 * NN;
    #pragma unroll
    for (int m = 0; m < MROWS; m++) {
        int i = i0 + tr + 32 * m;
        #pragma unroll
        for (int u = 0; u < 3; u++) {
            float lo, hi;
            upk2(acc[m][u], lo, hi);
            outp[(tc * 6 + 2 * u) * NN + i] = lo;
            outp[(tc * 6 + 2 * u + 1) * NN + i] = hi;
        }
    }
}

// ---- stress[b,p,q] = sum_i A[i][b*3+p] * Rsum[b*3+q][i]; one block per batch ----
__global__ void k_final(float* __restrict__ out) {
    int b = blockIdx.x, tid = threadIdx.x;
    float acc[9];
    #pragma unroll
    for (int u = 0; u < 9; u++) acc[u] = 0.f;
    const float* Ab = g_A + b * 3;
    for (int i = tid; i < NN; i += 256) {
        float a0 = Ab[i * 48], a1 = Ab[i * 48 + 1], a2 = Ab[i * 48 + 2];
        float r0 = 0.f, r1 = 0.f, r2 = 0.f;
        #pragma unroll
        for (int sp = 0; sp < KSPLIT; sp++) {
            const float* Rb = g_R + ((size_t)sp * 48 + b * 3) * NN + i;
            r0 += Rb[0];
            r1 += Rb[NN];
            r2 += Rb[2 * NN];
        }
        acc[0] = fmaf(a0, r0, acc[0]); acc[1] = fmaf(a0, r1, acc[1]); acc[2] = fmaf(a0, r2, acc[2]);
        acc[3] = fmaf(a1, r0, acc[3]); acc[4] = fmaf(a1, r1, acc[4]); acc[5] = fmaf(a1, r2, acc[5]);
        acc[6] = fmaf(a2, r0, acc[6]); acc[7] = fmaf(a2, r1, acc[7]); acc[8] = fmaf(a2, r2, acc[8]);
    }
    const unsigned full = 0xFFFFFFFFu;
    #pragma unroll
    for (int u = 0; u < 9; u++)
        #pragma unroll
        for (int off = 16; off > 0; off >>= 1) acc[u] += __shfl_down_sync(full, acc[u], off);
    __shared__ float red[8][9];
    int lane = tid & 31, wid = tid >> 5;
    if (lane == 0)
        #pragma unroll
        for (int u = 0; u < 9; u++) red[wid][u] = acc[u];
    __syncthreads();
    if (tid < 9) {
        float t = 0.f;
        #pragma unroll
        for (int w = 0; w < 8; w++) t += red[w][tid];
        out[b * 9 + tid] = t;
    }
}

// ---------------- launch ----------------
extern "C" void kernel_launch(void* const* d_in, const int* in_sizes, int n_in,
                              void* d_out, int out_size) {
    const float* F        = (const float*)d_in[0];
    const float* node_pos = (const float*)d_in[1];
    const int*   edge_src = (const int*)d_in[2];
    const int*   edge_dst = (const int*)d_in[3];
    const int*   edge_type= (const int*)d_in[4];
    const float* W_in     = (const float*)d_in[5];
    const float* fc1_0    = (const float*)d_in[6];
    const float* fc2_0    = (const float*)d_in[7];
    const float* W_0      = (const float*)d_in[8];
    const float* fc1_1    = (const float*)d_in[9];
    const float* fc2_1    = (const float*)d_in[10];
    const float* W_1      = (const float*)d_in[11];
    const float* W_out    = (const float*)d_in[12];
    const float* w        = (const float*)d_in[13];
    float* out = (float*)d_out;

    k_hist<<<NE / 1024, 256>>>(edge_dst, edge_src, edge_type, node_pos,
                               F, W_in, fc1_0, fc2_0, fc1_1, fc2_1);
    k_scan<<<1, 1024>>>();
    k_scatter_l0<<<SCAT_BLKS + NN / 8, 256>>>(edge_src, edge_dst, edge_type, W_0);
    k_layer1<<<NN, 256>>>(W_1);
    k_head<<<NN / 4, 256>>>(edge_src, edge_dst, W_out);
    k_gemm<<<dim3(NN / GROWS, KSPLIT), 256>>>(w);
    k_final<<<NB, 256>>>(out);
}

// round 16
// speedup vs baseline: 1.4580x; 1.4580x over previous
#include <cuda_runtime.h>

#define NB 16
#define NN 4096
#define NE 131072
#define NH 16
#define NT 3
#define NFC 20
#define BHD 256                     // B*H = 256 floats per node row
#define INV_SQRT_DEG 0.17677669529663687f   // 1/sqrt(E/N) = 1/sqrt(32)

#define KSPLIT 16                   // j-reduction splits in k_gemm
#define GROWS 128                   // rows per gemm block (512 blocks -> better waves/overlap)
#define MROWS (GROWS / 32)          // 4 row-fragments per thread
#define KJ 32                       // j-chunk per smem stage
#define WPITCH 34                   // Ws smem pitch (34 mod 32 == 2 -> LDS.64 conflict-free)
#define SCAT_BLKS (NE / 1024)       // 128 scatter blocks

typedef unsigned long long ull;

// ---------------- device scratch (static: no allocs allowed) ----------------
__device__ __align__(16) float g_h0[NN * BHD];     // final-h buffer (layer1 out)
__device__ __align__(16) float g_h1[NN * BHD];     // layer0 out
__device__ __align__(16) float g_A[NN * 48];       // a[i][b*3+p]
__device__ __align__(16) float g_C[NN * 48];       // c[j][b*3+q]
__device__ __align__(16) float g_R[KSPLIT * 48 * NN];  // R partials [sp][col][i]
__device__ int   g_cnt[NN];                        // zero-init; re-zeroed by k_scan
__device__ int   g_rowptr[NN + 1];
__device__ int   g_cursor[NN];
__device__ int   g_csr[NE];                        // src | (type<<16), sorted by dst
__device__ float g_ew[2 * NT];                     // per-layer per-type edge weight
__device__ float g_invF[NB * 9];
__device__ float g_P[NB * NH * 3];                 // P[b,k,j] = sum_i F[b,i,j] * W_in[i,k]
__device__ float g_S[NN * 3];                      // zero-init; re-zeroed by k_layer1

// ---------------- f32x2 packed-FMA helpers ----------------
__device__ __forceinline__ ull pk2(float lo, float hi) {
    ull r;
    asm("mov.b64 %0, {%1, %2};" : "=l"(r) : "f"(lo), "f"(hi));
    return r;
}
__device__ __forceinline__ void upk2(ull v, float& lo, float& hi) {
    asm("mov.b64 {%0, %1}, %2;" : "=f"(lo), "=f"(hi) : "l"(v));
}
__device__ __forceinline__ void fma2(ull& d, ull a, ull b) {
    asm("fma.rn.f32x2 %0, %1, %2, %0;" : "+l"(d) : "l"(a), "l"(b));
}

// ---- hist: cnt histogram + S accumulation + one-time init (block 0) ----
__global__ void k_hist(const int* __restrict__ edge_dst, const int* __restrict__ edge_src,
                       const int* __restrict__ edge_type, const float* __restrict__ node_pos,
                       const float* __restrict__ F, const float* __restrict__ W_in,
                       const float* __restrict__ fc10, const float* __restrict__ fc20,
                       const float* __restrict__ fc11, const float* __restrict__ fc21) {
    int tid = threadIdx.x;
    float ew0 = 0.f, ew1 = 0.f, ew2 = 0.f;
    #pragma unroll
    for (int f = 0; f < NFC; f++) {
        float c2 = __ldg(&fc20[f]);
        ew0 = fmaf(fmaxf(__ldg(&fc10[f]), 0.f), c2, ew0);
        ew1 = fmaf(fmaxf(__ldg(&fc10[NFC + f]), 0.f), c2, ew1);
        ew2 = fmaf(fmaxf(__ldg(&fc10[2 * NFC + f]), 0.f), c2, ew2);
    }
    int e0 = blockIdx.x * 1024 + tid * 4;
    int4 d4 = *(const int4*)(edge_dst + e0);
    int4 s4 = *(const int4*)(edge_src + e0);
    int4 t4 = *(const int4*)(edge_type + e0);
    int ds[4] = {d4.x, d4.y, d4.z, d4.w};
    int ss[4] = {s4.x, s4.y, s4.z, s4.w};
    int ts[4] = {t4.x, t4.y, t4.z, t4.w};
    #pragma unroll
    for (int u = 0; u < 4; u++) {
        int d = ds[u], s = ss[u], t = ts[u];
        atomicAdd(&g_cnt[d], 1);
        float w = (t == 0) ? ew0 : ((t == 1) ? ew1 : ew2);
        atomicAdd(&g_S[d * 3 + 0], w * __ldg(&node_pos[s * 3 + 0]));
        atomicAdd(&g_S[d * 3 + 1], w * __ldg(&node_pos[s * 3 + 1]));
        atomicAdd(&g_S[d * 3 + 2], w * __ldg(&node_pos[s * 3 + 2]));
    }
    if (blockIdx.x == 0) {
        if (tid < 6) {
            int l = tid / 3, t = tid % 3;
            const float* f1 = l ? fc11 : fc10;
            const float* f2 = l ? fc21 : fc20;
            float s = 0.f;
            #pragma unroll
            for (int f = 0; f < NFC; f++) s = fmaf(fmaxf(f1[t * NFC + f], 0.f), f2[f], s);
            g_ew[tid] = s;
        }
        if (tid >= 32 && tid < 32 + NB) {
            int b = tid - 32;
            const float* m = F + b * 9;
            float a00=m[0],a01=m[1],a02=m[2],a10=m[3],a11=m[4],a12=m[5],a20=m[6],a21=m[7],a22=m[8];
            float det = a00*(a11*a22-a12*a21) - a01*(a10*a22-a12*a20) + a02*(a10*a21-a11*a20);
            float id = 1.f / det;
            float* o = g_invF + b * 9;
            o[0]=(a11*a22-a12*a21)*id; o[1]=(a02*a21-a01*a22)*id; o[2]=(a01*a12-a02*a11)*id;
            o[3]=(a12*a20-a10*a22)*id; o[4]=(a00*a22-a02*a20)*id; o[5]=(a02*a10-a00*a12)*id;
            o[6]=(a10*a21-a11*a20)*id; o[7]=(a01*a20-a00*a21)*id; o[8]=(a00*a11-a01*a10)*id;
        }
        for (int idx = tid; idx < NB * NH * 3; idx += 256) {
            int b = idx / 48, r = idx % 48, k = r / 3, j = r % 3;
            float s = 0.f;
            #pragma unroll
            for (int i = 0; i < 3; i++) s = fmaf(F[b * 9 + i * 3 + j], W_in[i * 16 + k], s);
            g_P[idx] = s;
        }
    }
}

// ---------------- scan (1 block) + re-zero cnt ----------------
__global__ void k_scan() {
    int tid = threadIdx.x;
    int v[4]; int s = 0;
    #pragma unroll
    for (int j = 0; j < 4; j++) { v[j] = g_cnt[tid * 4 + j]; s += v[j]; }
    #pragma unroll
    for (int j = 0; j < 4; j++) g_cnt[tid * 4 + j] = 0;
    int lane = tid & 31, wid = tid >> 5;
    const unsigned full = 0xFFFFFFFFu;
    int x = s;
    #pragma unroll
    for (int off = 1; off < 32; off <<= 1) { int y = __shfl_up_sync(full, x, off); if (lane >= off) x += y; }
    __shared__ int swarp[32];
    if (lane == 31) swarp[wid] = x;
    __syncthreads();
    if (wid == 0) {
        int y = swarp[lane];
        #pragma unroll
        for (int off = 1; off < 32; off <<= 1) { int z = __shfl_up_sync(full, y, off); if (lane >= off) y += z; }
        swarp[lane] = y;
    }
    __syncthreads();
    int base = (x - s) + (wid > 0 ? swarp[wid - 1] : 0);
    int run = base;
    #pragma unroll
    for (int j = 0; j < 4; j++) {
        g_rowptr[tid * 4 + j] = run;
        g_cursor[tid * 4 + j] = run;
        run += v[j];
    }
    if (tid == 1023) g_rowptr[NN] = run;
}

// ---- fused: blocks [0,128) build CSR; blocks [128,640) run layer0 closed form ----
__global__ void k_scatter_l0(const int* __restrict__ edge_src,
                             const int* __restrict__ edge_dst,
                             const int* __restrict__ edge_type,
                             const float* __restrict__ W0) {
    int tid = threadIdx.x;
    if (blockIdx.x < SCAT_BLKS) {
        int e0 = blockIdx.x * 1024 + tid * 4;
        int4 d4 = *(const int4*)(edge_dst + e0);
        int4 s4 = *(const int4*)(edge_src + e0);
        int4 t4 = *(const int4*)(edge_type + e0);
        int ds[4] = {d4.x, d4.y, d4.z, d4.w};
        int ss[4] = {s4.x, s4.y, s4.z, s4.w};
        int ts[4] = {t4.x, t4.y, t4.z, t4.w};
        #pragma unroll
        for (int u = 0; u < 4; u++) {
            int pos = atomicAdd(&g_cursor[ds[u]], 1);
            g_csr[pos] = ss[u] | (ts[u] << 16);
        }
        return;
    }
    // ---- layer0 (8 nodes/block) ----
    int bid = blockIdx.x - SCAT_BLKS;
    __shared__ float sW[256], sS[24];
    __shared__ float sagg[8][256];
    sW[tid] = W0[tid];
    if (tid < 24) sS[tid] = g_S[bid * 24 + tid];
    float p0 = g_P[tid * 3], p1 = g_P[tid * 3 + 1], p2 = g_P[tid * 3 + 2];
    __syncthreads();
    #pragma unroll
    for (int nn = 0; nn < 8; nn++) {
        float acc = fmaf(p2, sS[nn * 3 + 2], fmaf(p1, sS[nn * 3 + 1], p0 * sS[nn * 3]));
        sagg[nn][tid] = acc * INV_SQRT_DEG;
    }
    __syncthreads();
    int b = tid >> 4, k = tid & 15;
    #pragma unroll
    for (int nn = 0; nn < 8; nn++) {
        const float* ar = &sagg[nn][b * 16];
        float s = 0.f;
        #pragma unroll
        for (int kk = 0; kk < 16; kk++) s = fmaf(ar[kk], sW[kk * 16 + k], s);
        g_h1[(bid * 8 + nn) * BHD + tid] = fmaxf(s, 0.f);
    }
}

// ---------------- layer 1: float4 gather, manual 4x unroll for MLP (R13 exact) ----------------
__global__ void k_layer1(const float* __restrict__ W1) {
    int n = blockIdx.x, tid = threadIdx.x;
    __shared__ float sW[256], sagg[256], sew[3];
    __shared__ __align__(16) float4 s4[4][64];
    __shared__ int sedge[128];
    sW[tid] = W1[tid];
    if (tid < 3) sew[tid] = g_ew[3 + tid];
    if (tid >= 32 && tid < 35) g_S[n * 3 + (tid - 32)] = 0.f;   // reset for next replay
    int g = tid >> 6, c4 = tid & 63;
    int start = g_rowptr[n], end = g_rowptr[n + 1];
    float4 acc = make_float4(0.f, 0.f, 0.f, 0.f);
    for (int base = start; base < end; base += 128) {
        int cnt = min(128, end - base);
        __syncthreads();
        if (tid < cnt) sedge[tid] = g_csr[base + tid];
        __syncthreads();
        int i = g;
        for (; i + 12 < cnt; i += 16) {
            int p0 = sedge[i], p1 = sedge[i + 4], p2 = sedge[i + 8], p3 = sedge[i + 12];
            float4 v0 = __ldg((const float4*)(g_h1 + (p0 & 0xFFFF) * BHD) + c4);
            float4 v1 = __ldg((const float4*)(g_h1 + (p1 & 0xFFFF) * BHD) + c4);
            float4 v2 = __ldg((const float4*)(g_h1 + (p2 & 0xFFFF) * BHD) + c4);
            float4 v3 = __ldg((const float4*)(g_h1 + (p3 & 0xFFFF) * BHD) + c4);
            float w0 = sew[p0 >> 16], w1 = sew[p1 >> 16];
            float w2 = sew[p2 >> 16], w3 = sew[p3 >> 16];
            acc.x = fmaf(w0, v0.x, acc.x); acc.y = fmaf(w0, v0.y, acc.y);
            acc.z = fmaf(w0, v0.z, acc.z); acc.w = fmaf(w0, v0.w, acc.w);
            acc.x = fmaf(w1, v1.x, acc.x); acc.y = fmaf(w1, v1.y, acc.y);
            acc.z = fmaf(w1, v1.z, acc.z); acc.w = fmaf(w1, v1.w, acc.w);
            acc.x = fmaf(w2, v2.x, acc.x); acc.y = fmaf(w2, v2.y, acc.y);
            acc.z = fmaf(w2, v2.z, acc.z); acc.w = fmaf(w2, v2.w, acc.w);
            acc.x = fmaf(w3, v3.x, acc.x); acc.y = fmaf(w3, v3.y, acc.y);
            acc.z = fmaf(w3, v3.z, acc.z); acc.w = fmaf(w3, v3.w, acc.w);
        }
        for (; i < cnt; i += 4) {
            int p = sedge[i];
            float w = sew[p >> 16];
            float4 v = __ldg((const float4*)(g_h1 + (p & 0xFFFF) * BHD) + c4);
            acc.x = fmaf(w, v.x, acc.x);
            acc.y = fmaf(w, v.y, acc.y);
            acc.z = fmaf(w, v.z, acc.z);
            acc.w = fmaf(w, v.w, acc.w);
        }
    }
    s4[g][c4] = acc;
    __syncthreads();
    {
        const float* sf = (const float*)s4;
        float a = sf[tid] + sf[256 + tid] + sf[512 + tid] + sf[768 + tid];
        sagg[tid] = a * INV_SQRT_DEG;
    }
    __syncthreads();
    int b = tid >> 4, k = tid & 15;
    const float* ar = &sagg[b * 16];
    float s = 0.f;
    #pragma unroll
    for (int kk = 0; kk < 16; kk++) s = fmaf(ar[kk], sW[kk * 16 + k], s);
    g_h0[n * BHD + tid] = fmaxf(s, 0.f);
}

// ---------------- head (4 edges/block): a & c for the first N edges ----------------
__global__ void k_head(const int* __restrict__ edge_src, const int* __restrict__ edge_dst,
                       const float* __restrict__ W_out) {
    int tid = threadIdx.x;
    int g = tid >> 6, c4 = tid & 63;
    int e0 = blockIdx.x * 4;
    __shared__ __align__(16) float4 sd4[4][64];
    __shared__ float sa[4][48];
    {
        int e = e0 + g;
        int src = edge_src[e], dst = edge_dst[e];
        float4 vs = __ldg((const float4*)(g_h0 + src * BHD) + c4);
        float4 vd = __ldg((const float4*)(g_h0 + dst * BHD) + c4);
        sd4[g][c4] = make_float4(vs.x - vd.x, vs.y - vd.y, vs.z - vd.z, vs.w - vd.w);
    }
    __syncthreads();
    if (tid < 192) {
        int eg = tid / 48, r = tid % 48;
        int b = r / 3, p = r % 3;
        const float* sd = (const float*)sd4[eg];
        float a = 0.f;
        #pragma unroll
        for (int k = 0; k < 16; k++) a = fmaf(sd[b * 16 + k], __ldg(&W_out[k * 3 + p]), a);
        sa[eg][r] = a;
        g_A[(e0 + eg) * 48 + r] = a;
    }
    __syncthreads();
    if (tid < 192) {
        int eg = tid / 48, r = tid % 48;
        int b = r / 3, q = r % 3;
        float c = 0.f;
        #pragma unroll
        for (int p = 0; p < 3; p++) c = fmaf(g_invF[b * 9 + q * 3 + p], sa[eg][b * 3 + p], c);
        g_C[(e0 + eg) * 48 + r] = c;
    }
}

// ---------------- R = W2 @ C via packed f32x2 FFMA; R stored [sp][col][i] ----------------
// GROWS=128: 512 blocks, 23.4 KB smem -> multiple blocks/SM overlap staging & math.
__global__ void __launch_bounds__(256) k_gemm(const float* __restrict__ W2) {
    int i0 = blockIdx.x * GROWS;
    int js = blockIdx.y;
    int j0base = js * (NN / KSPLIT);             // 256 j's per split
    __shared__ float Ws[GROWS * WPITCH];         // 128 x 34 floats = 17.4 KB
    __shared__ __align__(16) float Cs[KJ * 48];  // 6 KB
    int tid = threadIdx.x;
    int tr = tid & 31, tc = tid >> 5;

    ull acc[MROWS][3];
    #pragma unroll
    for (int m = 0; m < MROWS; m++)
        #pragma unroll
        for (int u = 0; u < 3; u++) acc[m][u] = 0ull;

    #pragma unroll 1
    for (int jc = 0; jc < (NN / KSPLIT) / KJ; jc++) {
        int j0 = j0base + jc * KJ;
        __syncthreads();
        {
            const float4* cg = (const float4*)(g_C + j0 * 48);
            float4* cs = (float4*)Cs;
            for (int t = tid; t < KJ * 12; t += 256) cs[t] = cg[t];
        }
        #pragma unroll
        for (int rep = 0; rep < GROWS * 8 / 256; rep++) {   // 4 reps
            int f = rep * 256 + tid;
            int r = f >> 3, c4 = f & 7;
            float4 w = *(const float4*)(W2 + (size_t)(i0 + r) * NN + j0 + c4 * 4);
            float* wd = &Ws[r * WPITCH + c4 * 4];
            wd[0] = w.x; wd[1] = w.y; wd[2] = w.z; wd[3] = w.w;
        }
        __syncthreads();
        #pragma unroll
        for (int jj = 0; jj < KJ; jj += 2) {
            float2 wv[MROWS];
            #pragma unroll
            for (int m = 0; m < MROWS; m++)
                wv[m] = *(const float2*)&Ws[(tr + 32 * m) * WPITCH + jj];
            const float2* c0 = (const float2*)&Cs[jj * 48 + tc * 6];
            const float2* c1 = (const float2*)&Cs[(jj + 1) * 48 + tc * 6];
            ull ca0 = ((const ull*)c0)[0];
            ull ca1 = ((const ull*)c0)[1];
            ull ca2 = ((const ull*)c0)[2];
            ull cb0 = ((const ull*)c1)[0];
            ull cb1 = ((const ull*)c1)[1];
            ull cb2 = ((const ull*)c1)[2];
            #pragma unroll
            for (int m = 0; m < MROWS; m++) {
                ull wlo = pk2(wv[m].x, wv[m].x);
                ull whi = pk2(wv[m].y, wv[m].y);
                fma2(acc[m][0], wlo, ca0);
                fma2(acc[m][1], wlo, ca1);
                fma2(acc[m][2], wlo, ca2);
                fma2(acc[m][0], whi, cb0);
                fma2(acc[m][1], whi, cb1);
                fma2(acc[m][2], whi, cb2);
            }
        }
    }
    // epilogue: R[sp][col][i], coalesced over i
    float* outp = g_R + (size_t)js * 48 * NN;
    #pragma unroll
    for (int m = 0; m < MROWS; m++) {
        int i = i0 + tr + 32 * m;
        #pragma unroll
        for (int u = 0; u < 3; u++) {
            float lo, hi;
            upk2(acc[m][u], lo, hi);
            outp[(tc * 6 + 2 * u) * NN + i] = lo;
            outp[(tc * 6 + 2 * u + 1) * NN + i] = hi;
        }
    }
}

// ---- stress[b,p,q] = sum_i A[i][b*3+p] * Rsum[b*3+q][i]; one block per batch ----
__global__ void k_final(float* __restrict__ out) {
    int b = blockIdx.x, tid = threadIdx.x;
    float acc[9];
    #pragma unroll
    for (int u = 0; u < 9; u++) acc[u] = 0.f;
    const float* Ab = g_A + b * 3;
    for (int i = tid; i < NN; i += 256) {
        float a0 = Ab[i * 48], a1 = Ab[i * 48 + 1], a2 = Ab[i * 48 + 2];
        float r0 = 0.f, r1 = 0.f, r2 = 0.f;
        #pragma unroll
        for (int sp = 0; sp < KSPLIT; sp++) {
            const float* Rb = g_R + ((size_t)sp * 48 + b * 3) * NN + i;
            r0 += Rb[0];
            r1 += Rb[NN];
            r2 += Rb[2 * NN];
        }
        acc[0] = fmaf(a0, r0, acc[0]); acc[1] = fmaf(a0, r1, acc[1]); acc[2] = fmaf(a0, r2, acc[2]);
        acc[3] = fmaf(a1, r0, acc[3]); acc[4] = fmaf(a1, r1, acc[4]); acc[5] = fmaf(a1, r2, acc[5]);
        acc[6] = fmaf(a2, r0, acc[6]); acc[7] = fmaf(a2, r1, acc[7]); acc[8] = fmaf(a2, r2, acc[8]);
    }
    const unsigned full = 0xFFFFFFFFu;
    #pragma unroll
    for (int u = 0; u < 9; u++)
        #pragma unroll
        for (int off = 16; off > 0; off >>= 1) acc[u] += __shfl_down_sync(full, acc[u], off);
    __shared__ float red[8][9];
    int lane = tid & 31, wid = tid >> 5;
    if (lane == 0)
        #pragma unroll
        for (int u = 0; u < 9; u++) red[wid][u] = acc[u];
    __syncthreads();
    if (tid < 9) {
        float t = 0.f;
        #pragma unroll
        for (int w = 0; w < 8; w++) t += red[w][tid];
        out[b * 9 + tid] = t;
    }
}

// ---------------- launch ----------------
extern "C" void kernel_launch(void* const* d_in, const int* in_sizes, int n_in,
                              void* d_out, int out_size) {
    const float* F        = (const float*)d_in[0];
    const float* node_pos = (const float*)d_in[1];
    const int*   edge_src = (const int*)d_in[2];
    const int*   edge_dst = (const int*)d_in[3];
    const int*   edge_type= (const int*)d_in[4];
    const float* W_in     = (const float*)d_in[5];
    const float* fc1_0    = (const float*)d_in[6];
    const float* fc2_0    = (const float*)d_in[7];
    const float* W_0      = (const float*)d_in[8];
    const float* fc1_1    = (const float*)d_in[9];
    const float* fc2_1    = (const float*)d_in[10];
    const float* W_1      = (const float*)d_in[11];
    const float* W_out    = (const float*)d_in[12];
    const float* w        = (const float*)d_in[13];
    float* out = (float*)d_out;

    k_hist<<<NE / 1024, 256>>>(edge_dst, edge_src, edge_type, node_pos,
                               F, W_in, fc1_0, fc2_0, fc1_1, fc2_1);
    k_scan<<<1, 1024>>>();
    k_scatter_l0<<<SCAT_BLKS + NN / 8, 256>>>(edge_src, edge_dst, edge_type, W_0);
    k_layer1<<<NN, 256>>>(W_1);
    k_head<<<NN / 4, 256>>>(edge_src, edge_dst, W_out);
    k_gemm<<<dim3(NN / GROWS, KSPLIT), 256>>>(w);
    k_final<<<NB, 256>>>(out);
}

// round 17
// speedup vs baseline: 1.8878x; 1.2948x over previous
#include <cuda_runtime.h>

#define NB 16
#define NN 4096
#define NE 131072
#define NH 16
#define NT 3
#define NFC 20
#define BHD 256                     // B*H = 256 floats per node row
#define INV_SQRT_DEG 0.17677669529663687f   // 1/sqrt(E/N) = 1/sqrt(32)

#define KSPLIT 16                   // j-reduction splits in k_gemm
#define GROWS 128                   // rows per gemm block (512 blocks)
#define MROWS (GROWS / 32)          // 4 row-fragments per thread
#define KJ 32                       // j-chunk per smem stage
#define WPITCH 34                   // Ws smem pitch (34 mod 32 == 2 -> LDS.64 conflict-free)
#define SCAT_BLKS (NE / 1024)       // 128 scatter blocks

typedef unsigned long long ull;

// ---------------- device scratch (static: no allocs allowed) ----------------
__device__ __align__(16) float g_h0[NN * BHD];     // final-h buffer (layer1 out)
__device__ __align__(16) float g_h1[NN * BHD];     // layer0 out
__device__ __align__(16) float g_A[NN * 48];       // a[i][b*3+p]
__device__ __align__(16) float g_C[NN * 48];       // c[j][b*3+q]
__device__ int   g_cnt[NN];                        // zero-init; re-zeroed by k_scan
__device__ int   g_rowptr[NN + 1];
__device__ int   g_cursor[NN];
__device__ int   g_csr[NE];                        // src | (type<<16), sorted by dst
__device__ float g_ew[2 * NT];                     // per-layer per-type edge weight
__device__ float g_invF[NB * 9];
__device__ float g_P[NB * NH * 3];                 // P[b,k,j] = sum_i F[b,i,j] * W_in[i,k]
__device__ float g_S[NN * 3];                      // zero-init; re-zeroed by k_layer1

// ---------------- f32x2 packed-FMA helpers ----------------
__device__ __forceinline__ ull pk2(float lo, float hi) {
    ull r;
    asm("mov.b64 %0, {%1, %2};" : "=l"(r) : "f"(lo), "f"(hi));
    return r;
}
__device__ __forceinline__ void upk2(ull v, float& lo, float& hi) {
    asm("mov.b64 {%0, %1}, %2;" : "=f"(lo), "=f"(hi) : "l"(v));
}
__device__ __forceinline__ void fma2(ull& d, ull a, ull b) {
    asm("fma.rn.f32x2 %0, %1, %2, %0;" : "+l"(d) : "l"(a), "l"(b));
}

// ---- hist: cnt histogram + S accumulation + one-time init (block 0) ----
__global__ void k_hist(const int* __restrict__ edge_dst, const int* __restrict__ edge_src,
                       const int* __restrict__ edge_type, const float* __restrict__ node_pos,
                       const float* __restrict__ F, const float* __restrict__ W_in,
                       const float* __restrict__ fc10, const float* __restrict__ fc20,
                       const float* __restrict__ fc11, const float* __restrict__ fc21) {
    int tid = threadIdx.x;
    float ew0 = 0.f, ew1 = 0.f, ew2 = 0.f;
    #pragma unroll
    for (int f = 0; f < NFC; f++) {
        float c2 = __ldg(&fc20[f]);
        ew0 = fmaf(fmaxf(__ldg(&fc10[f]), 0.f), c2, ew0);
        ew1 = fmaf(fmaxf(__ldg(&fc10[NFC + f]), 0.f), c2, ew1);
        ew2 = fmaf(fmaxf(__ldg(&fc10[2 * NFC + f]), 0.f), c2, ew2);
    }
    int e0 = blockIdx.x * 1024 + tid * 4;
    int4 d4 = *(const int4*)(edge_dst + e0);
    int4 s4 = *(const int4*)(edge_src + e0);
    int4 t4 = *(const int4*)(edge_type + e0);
    int ds[4] = {d4.x, d4.y, d4.z, d4.w};
    int ss[4] = {s4.x, s4.y, s4.z, s4.w};
    int ts[4] = {t4.x, t4.y, t4.z, t4.w};
    #pragma unroll
    for (int u = 0; u < 4; u++) {
        int d = ds[u], s = ss[u], t = ts[u];
        atomicAdd(&g_cnt[d], 1);
        float w = (t == 0) ? ew0 : ((t == 1) ? ew1 : ew2);
        atomicAdd(&g_S[d * 3 + 0], w * __ldg(&node_pos[s * 3 + 0]));
        atomicAdd(&g_S[d * 3 + 1], w * __ldg(&node_pos[s * 3 + 1]));
        atomicAdd(&g_S[d * 3 + 2], w * __ldg(&node_pos[s * 3 + 2]));
    }
    if (blockIdx.x == 0) {
        if (tid < 6) {
            int l = tid / 3, t = tid % 3;
            const float* f1 = l ? fc11 : fc10;
            const float* f2 = l ? fc21 : fc20;
            float s = 0.f;
            #pragma unroll
            for (int f = 0; f < NFC; f++) s = fmaf(fmaxf(f1[t * NFC + f], 0.f), f2[f], s);
            g_ew[tid] = s;
        }
        if (tid >= 32 && tid < 32 + NB) {
            int b = tid - 32;
            const float* m = F + b * 9;
            float a00=m[0],a01=m[1],a02=m[2],a10=m[3],a11=m[4],a12=m[5],a20=m[6],a21=m[7],a22=m[8];
            float det = a00*(a11*a22-a12*a21) - a01*(a10*a22-a12*a20) + a02*(a10*a21-a11*a20);
            float id = 1.f / det;
            float* o = g_invF + b * 9;
            o[0]=(a11*a22-a12*a21)*id; o[1]=(a02*a21-a01*a22)*id; o[2]=(a01*a12-a02*a11)*id;
            o[3]=(a12*a20-a10*a22)*id; o[4]=(a00*a22-a02*a20)*id; o[5]=(a02*a10-a00*a12)*id;
            o[6]=(a10*a21-a11*a20)*id; o[7]=(a01*a20-a00*a21)*id; o[8]=(a00*a11-a01*a10)*id;
        }
        for (int idx = tid; idx < NB * NH * 3; idx += 256) {
            int b = idx / 48, r = idx % 48, k = r / 3, j = r % 3;
            float s = 0.f;
            #pragma unroll
            for (int i = 0; i < 3; i++) s = fmaf(F[b * 9 + i * 3 + j], W_in[i * 16 + k], s);
            g_P[idx] = s;
        }
    }
}

// ---------------- scan (1 block) + re-zero cnt + zero stress output ----------------
__global__ void k_scan(float* __restrict__ out) {
    int tid = threadIdx.x;
    if (tid < NB * 9) out[tid] = 0.f;          // gemm accumulates stress atomically
    int v[4]; int s = 0;
    #pragma unroll
    for (int j = 0; j < 4; j++) { v[j] = g_cnt[tid * 4 + j]; s += v[j]; }
    #pragma unroll
    for (int j = 0; j < 4; j++) g_cnt[tid * 4 + j] = 0;
    int lane = tid & 31, wid = tid >> 5;
    const unsigned full = 0xFFFFFFFFu;
    int x = s;
    #pragma unroll
    for (int off = 1; off < 32; off <<= 1) { int y = __shfl_up_sync(full, x, off); if (lane >= off) x += y; }
    __shared__ int swarp[32];
    if (lane == 31) swarp[wid] = x;
    __syncthreads();
    if (wid == 0) {
        int y = swarp[lane];
        #pragma unroll
        for (int off = 1; off < 32; off <<= 1) { int z = __shfl_up_sync(full, y, off); if (lane >= off) y += z; }
        swarp[lane] = y;
    }
    __syncthreads();
    int base = (x - s) + (wid > 0 ? swarp[wid - 1] : 0);
    int run = base;
    #pragma unroll
    for (int j = 0; j < 4; j++) {
        g_rowptr[tid * 4 + j] = run;
        g_cursor[tid * 4 + j] = run;
        run += v[j];
    }
    if (tid == 1023) g_rowptr[NN] = run;
}

// ---- fused: blocks [0,128) build CSR; blocks [128,640) run layer0 closed form ----
__global__ void k_scatter_l0(const int* __restrict__ edge_src,
                             const int* __restrict__ edge_dst,
                             const int* __restrict__ edge_type,
                             const float* __restrict__ W0) {
    int tid = threadIdx.x;
    if (blockIdx.x < SCAT_BLKS) {
        int e0 = blockIdx.x * 1024 + tid * 4;
        int4 d4 = *(const int4*)(edge_dst + e0);
        int4 s4 = *(const int4*)(edge_src + e0);
        int4 t4 = *(const int4*)(edge_type + e0);
        int ds[4] = {d4.x, d4.y, d4.z, d4.w};
        int ss[4] = {s4.x, s4.y, s4.z, s4.w};
        int ts[4] = {t4.x, t4.y, t4.z, t4.w};
        #pragma unroll
        for (int u = 0; u < 4; u++) {
            int pos = atomicAdd(&g_cursor[ds[u]], 1);
            g_csr[pos] = ss[u] | (ts[u] << 16);
        }
        return;
    }
    // ---- layer0 (8 nodes/block) ----
    int bid = blockIdx.x - SCAT_BLKS;
    __shared__ float sW[256], sS[24];
    __shared__ float sagg[8][256];
    sW[tid] = W0[tid];
    if (tid < 24) sS[tid] = g_S[bid * 24 + tid];
    float p0 = g_P[tid * 3], p1 = g_P[tid * 3 + 1], p2 = g_P[tid * 3 + 2];
    __syncthreads();
    #pragma unroll
    for (int nn = 0; nn < 8; nn++) {
        float acc = fmaf(p2, sS[nn * 3 + 2], fmaf(p1, sS[nn * 3 + 1], p0 * sS[nn * 3]));
        sagg[nn][tid] = acc * INV_SQRT_DEG;
    }
    __syncthreads();
    int b = tid >> 4, k = tid & 15;
    #pragma unroll
    for (int nn = 0; nn < 8; nn++) {
        const float* ar = &sagg[nn][b * 16];
        float s = 0.f;
        #pragma unroll
        for (int kk = 0; kk < 16; kk++) s = fmaf(ar[kk], sW[kk * 16 + k], s);
        g_h1[(bid * 8 + nn) * BHD + tid] = fmaxf(s, 0.f);
    }
}

// ---------------- layer 1: float4 gather, manual 4x unroll for MLP ----------------
__global__ void k_layer1(const float* __restrict__ W1) {
    int n = blockIdx.x, tid = threadIdx.x;
    __shared__ float sW[256], sagg[256], sew[3];
    __shared__ __align__(16) float4 s4[4][64];
    __shared__ int sedge[128];
    sW[tid] = W1[tid];
    if (tid < 3) sew[tid] = g_ew[3 + tid];
    if (tid >= 32 && tid < 35) g_S[n * 3 + (tid - 32)] = 0.f;   // reset for next replay
    int g = tid >> 6, c4 = tid & 63;
    int start = g_rowptr[n], end = g_rowptr[n + 1];
    float4 acc = make_float4(0.f, 0.f, 0.f, 0.f);
    for (int base = start; base < end; base += 128) {
        int cnt = min(128, end - base);
        __syncthreads();
        if (tid < cnt) sedge[tid] = g_csr[base + tid];
        __syncthreads();
        int i = g;
        for (; i + 12 < cnt; i += 16) {
            int p0 = sedge[i], p1 = sedge[i + 4], p2 = sedge[i + 8], p3 = sedge[i + 12];
            float4 v0 = __ldg((const float4*)(g_h1 + (p0 & 0xFFFF) * BHD) + c4);
            float4 v1 = __ldg((const float4*)(g_h1 + (p1 & 0xFFFF) * BHD) + c4);
            float4 v2 = __ldg((const float4*)(g_h1 + (p2 & 0xFFFF) * BHD) + c4);
            float4 v3 = __ldg((const float4*)(g_h1 + (p3 & 0xFFFF) * BHD) + c4);
            float w0 = sew[p0 >> 16], w1 = sew[p1 >> 16];
            float w2 = sew[p2 >> 16], w3 = sew[p3 >> 16];
            acc.x = fmaf(w0, v0.x, acc.x); acc.y = fmaf(w0, v0.y, acc.y);
            acc.z = fmaf(w0, v0.z, acc.z); acc.w = fmaf(w0, v0.w, acc.w);
            acc.x = fmaf(w1, v1.x, acc.x); acc.y = fmaf(w1, v1.y, acc.y);
            acc.z = fmaf(w1, v1.z, acc.z); acc.w = fmaf(w1, v1.w, acc.w);
            acc.x = fmaf(w2, v2.x, acc.x); acc.y = fmaf(w2, v2.y, acc.y);
            acc.z = fmaf(w2, v2.z, acc.z); acc.w = fmaf(w2, v2.w, acc.w);
            acc.x = fmaf(w3, v3.x, acc.x); acc.y = fmaf(w3, v3.y, acc.y);
            acc.z = fmaf(w3, v3.z, acc.z); acc.w = fmaf(w3, v3.w, acc.w);
        }
        for (; i < cnt; i += 4) {
            int p = sedge[i];
            float w = sew[p >> 16];
            float4 v = __ldg((const float4*)(g_h1 + (p & 0xFFFF) * BHD) + c4);
            acc.x = fmaf(w, v.x, acc.x);
            acc.y = fmaf(w, v.y, acc.y);
            acc.z = fmaf(w, v.z, acc.z);
            acc.w = fmaf(w, v.w, acc.w);
        }
    }
    s4[g][c4] = acc;
    __syncthreads();
    {
        const float* sf = (const float*)s4;
        float a = sf[tid] + sf[256 + tid] + sf[512 + tid] + sf[768 + tid];
        sagg[tid] = a * INV_SQRT_DEG;
    }
    __syncthreads();
    int b = tid >> 4, k = tid & 15;
    const float* ar = &sagg[b * 16];
    float s = 0.f;
    #pragma unroll
    for (int kk = 0; kk < 16; kk++) s = fmaf(ar[kk], sW[kk * 16 + k], s);
    g_h0[n * BHD + tid] = fmaxf(s, 0.f);
}

// ---------------- head (4 edges/block): a & c for the first N edges ----------------
__global__ void k_head(const int* __restrict__ edge_src, const int* __restrict__ edge_dst,
                       const float* __restrict__ W_out) {
    int tid = threadIdx.x;
    int g = tid >> 6, c4 = tid & 63;
    int e0 = blockIdx.x * 4;
    __shared__ __align__(16) float4 sd4[4][64];
    __shared__ float sa[4][48];
    {
        int e = e0 + g;
        int src = edge_src[e], dst = edge_dst[e];
        float4 vs = __ldg((const float4*)(g_h0 + src * BHD) + c4);
        float4 vd = __ldg((const float4*)(g_h0 + dst * BHD) + c4);
        sd4[g][c4] = make_float4(vs.x - vd.x, vs.y - vd.y, vs.z - vd.z, vs.w - vd.w);
    }
    __syncthreads();
    if (tid < 192) {
        int eg = tid / 48, r = tid % 48;
        int b = r / 3, p = r % 3;
        const float* sd = (const float*)sd4[eg];
        float a = 0.f;
        #pragma unroll
        for (int k = 0; k < 16; k++) a = fmaf(sd[b * 16 + k], __ldg(&W_out[k * 3 + p]), a);
        sa[eg][r] = a;
        g_A[(e0 + eg) * 48 + r] = a;
    }
    __syncthreads();
    if (tid < 192) {
        int eg = tid / 48, r = tid % 48;
        int b = r / 3, q = r % 3;
        float c = 0.f;
        #pragma unroll
        for (int p = 0; p < 3; p++) c = fmaf(g_invF[b * 9 + q * 3 + p], sa[eg][b * 3 + p], c);
        g_C[(e0 + eg) * 48 + r] = c;
    }
}

// ---- gemm + fused stress contraction.  Each CTA: rows [i0,i0+128), K-split js.
// Thread (tr,tc): rows i0+tr+32m, cols tc*6..tc*6+5 == (b,q) pairs for b=2tc,2tc+1.
// stress[b][p][q] += A[i][b*3+p] * r[i][b*3+q]; A indices == the same 6-col window.
__global__ void __launch_bounds__(256) k_gemm(const float* __restrict__ W2,
                                              float* __restrict__ out) {
    int i0 = blockIdx.x * GROWS;
    int js = blockIdx.y;
    int j0base = js * (NN / KSPLIT);             // 256 j's per split
    __shared__ float Ws[GROWS * WPITCH];         // 128 x 34 floats = 17.4 KB
    __shared__ __align__(16) float Cs[KJ * 48];  // 6 KB
    int tid = threadIdx.x;
    int tr = tid & 31, tc = tid >> 5;

    ull acc[MROWS][3];
    #pragma unroll
    for (int m = 0; m < MROWS; m++)
        #pragma unroll
        for (int u = 0; u < 3; u++) acc[m][u] = 0ull;

    #pragma unroll 1
    for (int jc = 0; jc < (NN / KSPLIT) / KJ; jc++) {
        int j0 = j0base + jc * KJ;
        __syncthreads();
        {
            const float4* cg = (const float4*)(g_C + j0 * 48);
            float4* cs = (float4*)Cs;
            for (int t = tid; t < KJ * 12; t += 256) cs[t] = cg[t];
        }
        #pragma unroll
        for (int rep = 0; rep < GROWS * 8 / 256; rep++) {   // 4 reps
            int f = rep * 256 + tid;
            int r = f >> 3, c4 = f & 7;
            float4 w = *(const float4*)(W2 + (size_t)(i0 + r) * NN + j0 + c4 * 4);
            float* wd = &Ws[r * WPITCH + c4 * 4];
            wd[0] = w.x; wd[1] = w.y; wd[2] = w.z; wd[3] = w.w;
        }
        __syncthreads();
        #pragma unroll
        for (int jj = 0; jj < KJ; jj += 2) {
            float2 wv[MROWS];
            #pragma unroll
            for (int m = 0; m < MROWS; m++)
                wv[m] = *(const float2*)&Ws[(tr + 32 * m) * WPITCH + jj];
            const float2* c0 = (const float2*)&Cs[jj * 48 + tc * 6];
            const float2* c1 = (const float2*)&Cs[(jj + 1) * 48 + tc * 6];
            ull ca0 = ((const ull*)c0)[0];
            ull ca1 = ((const ull*)c0)[1];
            ull ca2 = ((const ull*)c0)[2];
            ull cb0 = ((const ull*)c1)[0];
            ull cb1 = ((const ull*)c1)[1];
            ull cb2 = ((const ull*)c1)[2];
            #pragma unroll
            for (int m = 0; m < MROWS; m++) {
                ull wlo = pk2(wv[m].x, wv[m].x);
                ull whi = pk2(wv[m].y, wv[m].y);
                fma2(acc[m][0], wlo, ca0);
                fma2(acc[m][1], wlo, ca1);
                fma2(acc[m][2], wlo, ca2);
                fma2(acc[m][0], whi, cb0);
                fma2(acc[m][1], whi, cb1);
                fma2(acc[m][2], whi, cb2);
            }
        }
    }
    // ---- fused epilogue: contract rows with A, reduce per-warp, atomicAdd stress ----
    float sp[18];
    #pragma unroll
    for (int v = 0; v < 18; v++) sp[v] = 0.f;
    #pragma unroll
    for (int m = 0; m < MROWS; m++) {
        int i = i0 + tr + 32 * m;
        float rv[6];
        #pragma unroll
        for (int u = 0; u < 3; u++) upk2(acc[m][u], rv[2 * u], rv[2 * u + 1]);
        const float* ap = g_A + (size_t)i * 48 + tc * 6;
        float2 a01 = *(const float2*)(ap);
        float2 a23 = *(const float2*)(ap + 2);
        float2 a45 = *(const float2*)(ap + 4);
        float av[6] = {a01.x, a01.y, a23.x, a23.y, a45.x, a45.y};
        #pragma unroll
        for (int bl = 0; bl < 2; bl++)
            #pragma unroll
            for (int p = 0; p < 3; p++)
                #pragma unroll
                for (int q = 0; q < 3; q++)
                    sp[bl * 9 + p * 3 + q] = fmaf(av[bl * 3 + p], rv[bl * 3 + q],
                                                  sp[bl * 9 + p * 3 + q]);
    }
    const unsigned full = 0xFFFFFFFFu;
    #pragma unroll
    for (int v = 0; v < 18; v++)
        #pragma unroll
        for (int off = 16; off > 0; off >>= 1)
            sp[v] += __shfl_down_sync(full, sp[v], off);
    if (tr == 0) {
        #pragma unroll
        for (int bl = 0; bl < 2; bl++)
            #pragma unroll
            for (int r = 0; r < 9; r++)
                atomicAdd(&out[(2 * tc + bl) * 9 + r], sp[bl * 9 + r]);
    }
}

// ---------------- launch ----------------
extern "C" void kernel_launch(void* const* d_in, const int* in_sizes, int n_in,
                              void* d_out, int out_size) {
    const float* F        = (const float*)d_in[0];
    const float* node_pos = (const float*)d_in[1];
    const int*   edge_src = (const int*)d_in[2];
    const int*   edge_dst = (const int*)d_in[3];
    const int*   edge_type= (const int*)d_in[4];
    const float* W_in     = (const float*)d_in[5];
    const float* fc1_0    = (const float*)d_in[6];
    const float* fc2_0    = (const float*)d_in[7];
    const float* W_0      = (const float*)d_in[8];
    const float* fc1_1    = (const float*)d_in[9];
    const float* fc2_1    = (const float*)d_in[10];
    const float* W_1      = (const float*)d_in[11];
    const float* W_out    = (const float*)d_in[12];
    const float* w        = (const float*)d_in[13];
    float* out = (float*)d_out;

    k_hist<<<NE / 1024, 256>>>(edge_dst, edge_src, edge_type, node_pos,
                               F, W_in, fc1_0, fc2_0, fc1_1, fc2_1);
    k_scan<<<1, 1024>>>(out);
    k_scatter_l0<<<SCAT_BLKS + NN / 8, 256>>>(edge_src, edge_dst, edge_type, W_0);
    k_layer1<<<NN, 256>>>(W_1);
    k_head<<<NN / 4, 256>>>(edge_src, edge_dst, W_out);
    k_gemm<<<dim3(NN / GROWS, KSPLIT), 256>>>(w, out);
}